// round 1
// baseline (speedup 1.0000x reference)
#include <cuda_runtime.h>

#define NN 100000     // nodes in original graph
#define EO 600000     // edges in original graph == nodes of line graph
#define EL 1200000    // edges in line graph
#define HD 128
#define OD 64

// ---------------- scratch (device globals; no runtime allocation) ----------
static __device__ float g_nodeA[(size_t)NN * HD];
static __device__ float g_nodeB[(size_t)NN * HD];
static __device__ float g_nodeC[(size_t)NN * HD];
static __device__ float g_edgeA[(size_t)EO * HD];
static __device__ float g_edgeB[(size_t)EO * HD];
static __device__ float g_edgeC[(size_t)EO * HD];
static __device__ float g_Wf[HD * HD];
static __device__ float g_bf[HD];

// ---------------- BN fold: Wf[k][j] = W1[k][j]*s_j ; bf[j]=b1*s+bb-m*s -----
__global__ void fold_bn_kernel(const float* __restrict__ W1,
                               const float* __restrict__ b1,
                               const float* __restrict__ g,
                               const float* __restrict__ bb,
                               const float* __restrict__ m,
                               const float* __restrict__ v,
                               float* __restrict__ Wf,
                               float* __restrict__ bf) {
    int idx = blockIdx.x * blockDim.x + threadIdx.x;   // 64*256 = 16384
    int j = idx & (HD - 1);
    float s = g[j] * rsqrtf(v[j] + 1e-5f);
    Wf[idx] = W1[idx] * s;
    if (idx < HD) bf[idx] = b1[idx] * s + bb[idx] - m[idx] * s;
}

// ---------------- float4 copy (agg := x, provides GIN self-term) -----------
__global__ void copy4_kernel(const float4* __restrict__ s,
                             float4* __restrict__ d, int n) {
    int i = blockIdx.x * 256 + threadIdx.x;
    if (i < n) d[i] = s[i];
}

// ---------------- scatter-add: agg[dst] += x[src], 32 threads/edge ---------
__global__ void scatter_add_kernel(const int* __restrict__ srcs,
                                   const int* __restrict__ dsts,
                                   const float* __restrict__ x,
                                   float* __restrict__ agg, int E) {
    unsigned t = blockIdx.x * 256u + threadIdx.x;
    unsigned e = t >> 5;
    unsigned lane = t & 31u;
    if (e >= (unsigned)E) return;
    int s = srcs[e];
    int d = dsts[e];
    float4 vv = ((const float4*)(x + (size_t)s * HD))[lane];
    float* dp = agg + (size_t)d * HD + lane * 4;
    atomicAdd(dp + 0, vv.x);
    atomicAdd(dp + 1, vv.y);
    atomicAdd(dp + 2, vv.z);
    atomicAdd(dp + 3, vv.w);
}

// ---------------- h[e] = y[ep[e][0]] + y[ep[e][1]] -------------------------
__global__ void pair_gather_kernel(const int* __restrict__ ep,
                                   const float* __restrict__ y,
                                   float* __restrict__ h, int E) {
    unsigned t = blockIdx.x * 256u + threadIdx.x;
    unsigned e = t >> 5;
    unsigned lane = t & 31u;
    if (e >= (unsigned)E) return;
    int i0 = ep[2 * e];
    int i1 = ep[2 * e + 1];
    float4 a = ((const float4*)(y + (size_t)i0 * HD))[lane];
    float4 b = ((const float4*)(y + (size_t)i1 * HD))[lane];
    a.x += b.x; a.y += b.y; a.z += b.z; a.w += b.w;
    ((float4*)(h + (size_t)e * HD))[lane] = a;
}

// ---------------- fused GEMM + bias (+ReLU): C = act(A @ W + bias) ---------
// A: [M,128] row-major, W: [128,N] row-major, block tile 64 x N, 256 thr.
#define AS_STRIDE 132   // padded row stride (floats) -> conflict-free LDS

template <int N, bool RELU>
__global__ __launch_bounds__(256) void gemm_bias_kernel(
    const float* __restrict__ A, const float* __restrict__ W,
    const float* __restrict__ bias, float* __restrict__ C, int M) {
    extern __shared__ float sm[];
    float* Ws = sm;                 // HD * N floats
    float* As = sm + HD * N;        // 64 * AS_STRIDE floats

    const int tid = threadIdx.x;
    const int m0 = blockIdx.x * 64;

    // load W (whole [128,N]) into smem
    const float4* W4 = (const float4*)W;
    float4* Ws4 = (float4*)Ws;
    const int WN4 = HD * N / 4;
#pragma unroll
    for (int i = tid; i < WN4; i += 256) Ws4[i] = W4[i];

    // load A tile [64,128] into padded smem
    const float4* A4 = (const float4*)A;
    for (int i = tid; i < 64 * 32; i += 256) {
        int r = i >> 5;
        int c = i & 31;
        int row = m0 + r;
        float4 vv = make_float4(0.f, 0.f, 0.f, 0.f);
        if (row < M) vv = A4[(size_t)row * 32 + c];
        *(float4*)(As + r * AS_STRIDE + c * 4) = vv;
    }
    __syncthreads();

    constexpr int TN = N / 16;       // 8 for N=128, 4 for N=64
    const int tc = tid & 15;
    const int tr = tid >> 4;

    float acc[4][TN];
#pragma unroll
    for (int r = 0; r < 4; ++r)
#pragma unroll
        for (int c = 0; c < TN; ++c) acc[r][c] = 0.f;

    const float* a_base = As + tr * 4 * AS_STRIDE;
    const float* w_base = Ws + tc * TN;

#pragma unroll 4
    for (int k = 0; k < HD; ++k) {
        float av[4];
#pragma unroll
        for (int r = 0; r < 4; ++r) av[r] = a_base[r * AS_STRIDE + k];
        float wv[TN];
#pragma unroll
        for (int c4 = 0; c4 < TN / 4; ++c4) {
            float4 w = *(const float4*)(w_base + k * N + c4 * 4);
            wv[c4 * 4 + 0] = w.x;
            wv[c4 * 4 + 1] = w.y;
            wv[c4 * 4 + 2] = w.z;
            wv[c4 * 4 + 3] = w.w;
        }
#pragma unroll
        for (int r = 0; r < 4; ++r)
#pragma unroll
            for (int c = 0; c < TN; ++c)
                acc[r][c] = fmaf(av[r], wv[c], acc[r][c]);
    }

    float bv[TN];
#pragma unroll
    for (int c = 0; c < TN; ++c) bv[c] = bias[tc * TN + c];

#pragma unroll
    for (int r = 0; r < 4; ++r) {
        int row = m0 + tr * 4 + r;
        if (row < M) {
#pragma unroll
            for (int c4 = 0; c4 < TN / 4; ++c4) {
                float4 o;
                float o0 = acc[r][c4 * 4 + 0] + bv[c4 * 4 + 0];
                float o1 = acc[r][c4 * 4 + 1] + bv[c4 * 4 + 1];
                float o2 = acc[r][c4 * 4 + 2] + bv[c4 * 4 + 2];
                float o3 = acc[r][c4 * 4 + 3] + bv[c4 * 4 + 3];
                if (RELU) {
                    o0 = fmaxf(o0, 0.f); o1 = fmaxf(o1, 0.f);
                    o2 = fmaxf(o2, 0.f); o3 = fmaxf(o3, 0.f);
                }
                o.x = o0; o.y = o1; o.z = o2; o.w = o3;
                *(float4*)(C + (size_t)row * N + tc * TN + c4 * 4) = o;
            }
        }
    }
}

// ---------------------------------------------------------------------------
extern "C" void kernel_launch(void* const* d_in, const int* in_sizes, int n_in,
                              void* d_out, int out_size) {
    const int*   edge_index = (const int*)d_in[0];    // (2, EL)
    const float* x_orig     = (const float*)d_in[1];  // (NN, HD)
    const int*   ei_orig    = (const int*)d_in[2];    // (2, EO)
    const int*   edge_pairs = (const int*)d_in[3];    // (EO, 2)
    const float* init_W1 = (const float*)d_in[4];
    const float* init_b1 = (const float*)d_in[5];
    const float* init_g  = (const float*)d_in[6];
    const float* init_bb = (const float*)d_in[7];
    const float* init_m  = (const float*)d_in[8];
    const float* init_v  = (const float*)d_in[9];
    const float* init_W2 = (const float*)d_in[10];
    const float* init_b2 = (const float*)d_in[11];
    const float* gin_W1  = (const float*)d_in[12];
    const float* gin_b1  = (const float*)d_in[13];
    const float* gin_g   = (const float*)d_in[14];
    const float* gin_bb  = (const float*)d_in[15];
    const float* gin_m   = (const float*)d_in[16];
    const float* gin_v   = (const float*)d_in[17];
    const float* gin_W2  = (const float*)d_in[18];
    const float* gin_b2  = (const float*)d_in[19];
    const float* mlp_W1  = (const float*)d_in[20];
    const float* mlp_b1  = (const float*)d_in[21];
    const float* mlp_g   = (const float*)d_in[22];
    const float* mlp_bb  = (const float*)d_in[23];
    const float* mlp_m   = (const float*)d_in[24];
    const float* mlp_v   = (const float*)d_in[25];
    const float* mlp_W2  = (const float*)d_in[26];
    const float* mlp_b2  = (const float*)d_in[27];
    const float* out_W   = (const float*)d_in[28];
    const float* out_b   = (const float*)d_in[29];
    float* out = (float*)d_out;

    float *nodeA, *nodeB, *nodeC, *edgeA, *edgeB, *edgeC, *Wf, *bf;
    cudaGetSymbolAddress((void**)&nodeA, g_nodeA);
    cudaGetSymbolAddress((void**)&nodeB, g_nodeB);
    cudaGetSymbolAddress((void**)&nodeC, g_nodeC);
    cudaGetSymbolAddress((void**)&edgeA, g_edgeA);
    cudaGetSymbolAddress((void**)&edgeB, g_edgeB);
    cudaGetSymbolAddress((void**)&edgeC, g_edgeC);
    cudaGetSymbolAddress((void**)&Wf, g_Wf);
    cudaGetSymbolAddress((void**)&bf, g_bf);

    const int SMEM128 = (HD * HD + 64 * AS_STRIDE) * 4;  // 99328 B
    const int SMEM64  = (HD * OD + 64 * AS_STRIDE) * 4;  // 66560 B
    cudaFuncSetAttribute(gemm_bias_kernel<HD, true>,
                         cudaFuncAttributeMaxDynamicSharedMemorySize, SMEM128);
    cudaFuncSetAttribute(gemm_bias_kernel<HD, false>,
                         cudaFuncAttributeMaxDynamicSharedMemorySize, SMEM128);
    cudaFuncSetAttribute(gemm_bias_kernel<OD, false>,
                         cudaFuncAttributeMaxDynamicSharedMemorySize, SMEM64);

    const int gridN = (NN + 63) / 64;      // node-stage GEMM blocks
    const int gridE = (EO + 63) / 64;      // edge-stage GEMM blocks
    const int cpN = (NN * 32 + 255) / 256; // float4 copy, node feats
    const int cpE = (EO * 32 + 255) / 256;
    const int scO = ((unsigned)EO * 32u + 255u) / 256u;  // 32 thr/edge
    const int scL = ((unsigned)EL * 32u + 255u) / 256u;

    // ---------------- Stage A: 2 GIN layers on original graph --------------
    const float* x = x_orig;
    for (int i = 0; i < 2; ++i) {
        copy4_kernel<<<cpN, 256>>>((const float4*)x, (float4*)nodeC, NN * 32);
        scatter_add_kernel<<<scO, 256>>>(ei_orig, ei_orig + EO, x, nodeC, EO);
        fold_bn_kernel<<<64, 256>>>(init_W1 + i * HD * HD, init_b1 + i * HD,
                                    init_g + i * HD, init_bb + i * HD,
                                    init_m + i * HD, init_v + i * HD, Wf, bf);
        gemm_bias_kernel<HD, true><<<gridN, 256, SMEM128>>>(nodeC, Wf, bf, nodeB, NN);
        gemm_bias_kernel<HD, true><<<gridN, 256, SMEM128>>>(
            nodeB, init_W2 + i * HD * HD, init_b2 + i * HD, nodeA, NN);
        x = nodeA;
    }

    // ---------------- Stage B: node MLP (computed once per node) -----------
    fold_bn_kernel<<<64, 256>>>(mlp_W1, mlp_b1, mlp_g, mlp_bb, mlp_m, mlp_v, Wf, bf);
    gemm_bias_kernel<HD, true><<<gridN, 256, SMEM128>>>(nodeA, Wf, bf, nodeB, NN);
    gemm_bias_kernel<HD, false><<<gridN, 256, SMEM128>>>(nodeB, mlp_W2, mlp_b2, nodeC, NN);

    // ---------------- Stage C: lift onto line graph ------------------------
    pair_gather_kernel<<<scO, 256>>>(edge_pairs, nodeC, edgeA, EO);

    // ---------------- Stage D: 2 GIN layers on line graph ------------------
    for (int i = 0; i < 2; ++i) {
        copy4_kernel<<<cpE, 256>>>((const float4*)edgeA, (float4*)edgeB, EO * 32);
        scatter_add_kernel<<<scL, 256>>>(edge_index, edge_index + EL, edgeA, edgeB, EL);
        fold_bn_kernel<<<64, 256>>>(gin_W1 + i * HD * HD, gin_b1 + i * HD,
                                    gin_g + i * HD, gin_bb + i * HD,
                                    gin_m + i * HD, gin_v + i * HD, Wf, bf);
        gemm_bias_kernel<HD, true><<<gridE, 256, SMEM128>>>(edgeB, Wf, bf, edgeC, EO);
        gemm_bias_kernel<HD, true><<<gridE, 256, SMEM128>>>(
            edgeC, gin_W2 + i * HD * HD, gin_b2 + i * HD, edgeA, EO);
    }

    // ---------------- Stage E: output head ---------------------------------
    gemm_bias_kernel<OD, false><<<gridE, 256, SMEM64>>>(edgeA, out_W, out_b, out, EO);
}

// round 2
// speedup vs baseline: 2.3716x; 2.3716x over previous
#include <cuda_runtime.h>
#include <cuda_bf16.h>
#include <cstdint>

#define NN 100000     // nodes in original graph
#define EO 600000     // edge-nodes (line graph)
#define EL 1200000    // edges in line graph
#define HD 128
#define OD 64
#define SA 136        // smem row stride (bf16 elems) -> conflict-spread ldmatrix

// ---------------- scratch (device globals; no runtime allocation) ----------
static __device__ float g_nodeA[(size_t)NN * HD];
static __device__ float g_nodeC[(size_t)NN * HD];
static __device__ float g_edgeA[(size_t)EO * HD];
static __device__ float g_edgeB[(size_t)EO * HD];
static __device__ float g_bf[HD];
static __device__ __nv_bfloat16 g_W1h[HD * HD], g_W1l[HD * HD];
static __device__ __nv_bfloat16 g_W2h[HD * HD], g_W2l[HD * HD];
static __device__ __nv_bfloat16 g_Woh[HD * OD], g_Wol[HD * OD];

// ---------------- PTX helpers ----------------------------------------------
__device__ __forceinline__ void ldsm4(uint32_t* r, const void* p) {
    uint32_t a = (uint32_t)__cvta_generic_to_shared(p);
    asm volatile("ldmatrix.sync.aligned.m8n8.x4.shared.b16 {%0,%1,%2,%3}, [%4];"
                 : "=r"(r[0]), "=r"(r[1]), "=r"(r[2]), "=r"(r[3]) : "r"(a));
}

__device__ __forceinline__ void mma_bf16(float* d, const uint32_t* a,
                                         uint32_t b0, uint32_t b1) {
    asm volatile(
        "mma.sync.aligned.m16n8k16.row.col.f32.bf16.bf16.f32 "
        "{%0,%1,%2,%3}, {%4,%5,%6,%7}, {%8,%9}, {%0,%1,%2,%3};"
        : "+f"(d[0]), "+f"(d[1]), "+f"(d[2]), "+f"(d[3])
        : "r"(a[0]), "r"(a[1]), "r"(a[2]), "r"(a[3]), "r"(b0), "r"(b1));
}

__device__ __forceinline__ void split_store2(float x0, float x1,
                                             __nv_bfloat16* ph,
                                             __nv_bfloat16* pl) {
    __nv_bfloat16 h0 = __float2bfloat16(x0);
    __nv_bfloat16 h1 = __float2bfloat16(x1);
    __nv_bfloat16 l0 = __float2bfloat16(x0 - __bfloat162float(h0));
    __nv_bfloat16 l1 = __float2bfloat16(x1 - __bfloat162float(h1));
    *(__nv_bfloat162*)ph = __halves2bfloat162(h0, h1);
    *(__nv_bfloat162*)pl = __halves2bfloat162(l0, l1);
}

// one 128x128 @ 128x128 pass from smem (A split hi/lo, W split hi/lo)
__device__ __forceinline__ void gemm_pass(
    const __nv_bfloat16* As_h, const __nv_bfloat16* As_l,
    const __nv_bfloat16* Wh, const __nv_bfloat16* Wl,
    int rowBase, int colBase, int lrow, int lkoff, float (&acc)[4][4][4]) {
#pragma unroll
    for (int mi = 0; mi < 4; ++mi)
#pragma unroll
        for (int ni = 0; ni < 4; ++ni)
#pragma unroll
            for (int q = 0; q < 4; ++q) acc[mi][ni][q] = 0.f;

#pragma unroll
    for (int ks = 0; ks < 8; ++ks) {
        const int k0 = ks * 16 + lkoff;
        uint32_t ah[4][4], al[4][4];
#pragma unroll
        for (int mi = 0; mi < 4; ++mi) {
            const int base = (rowBase + mi * 16 + lrow) * SA + k0;
            ldsm4(ah[mi], As_h + base);
            ldsm4(al[mi], As_l + base);
        }
        uint32_t bh[2][4], bl[2][4];
#pragma unroll
        for (int nj = 0; nj < 2; ++nj) {
            const int base = (colBase + nj * 16 + lrow) * SA + k0;
            ldsm4(bh[nj], Wh + base);
            ldsm4(bl[nj], Wl + base);
        }
#pragma unroll
        for (int mi = 0; mi < 4; ++mi)
#pragma unroll
            for (int ni = 0; ni < 4; ++ni) {
                const int nj = ni >> 1, hh = ni & 1;
                mma_bf16(acc[mi][ni], ah[mi], bh[nj][hh], bh[nj][hh + 2]);
                mma_bf16(acc[mi][ni], ah[mi], bl[nj][hh], bl[nj][hh + 2]);
                mma_bf16(acc[mi][ni], al[mi], bh[nj][hh], bh[nj][hh + 2]);
            }
    }
}

// copy packed [128][128] bf16 gmem weight into padded smem [128][SA]
__device__ __forceinline__ void load_w_smem(const __nv_bfloat16* g,
                                            __nv_bfloat16* s, int tid) {
#pragma unroll
    for (int i = tid; i < 2048; i += 256) {
        int r = i >> 4, c = i & 15;
        *(uint4*)(s + r * SA + c * 8) = ((const uint4*)g)[i];
    }
}

// ---------------- fused GIN layer: relu(bn(AW1+b1)) @ W2 + b2 (+relu) ------
template <bool RELU2>
__global__ __launch_bounds__(256, 1) void fused2_mma(
    const float* __restrict__ A,
    const __nv_bfloat16* __restrict__ W1h, const __nv_bfloat16* __restrict__ W1l,
    const __nv_bfloat16* __restrict__ W2h, const __nv_bfloat16* __restrict__ W2l,
    const float* __restrict__ b1, const float* __restrict__ b2,
    float* __restrict__ C, int M) {
    extern __shared__ char smem[];
    __nv_bfloat16* As_h = (__nv_bfloat16*)smem;
    __nv_bfloat16* As_l = As_h + 128 * SA;
    __nv_bfloat16* Wah = As_l + 128 * SA;
    __nv_bfloat16* Wal = Wah + 128 * SA;
    __nv_bfloat16* Wbh = Wal + 128 * SA;
    __nv_bfloat16* Wbl = Wbh + 128 * SA;

    const int tid = threadIdx.x;
    const int m0 = blockIdx.x * 128;

    load_w_smem(W1h, Wah, tid);
    load_w_smem(W1l, Wal, tid);
    load_w_smem(W2h, Wbh, tid);
    load_w_smem(W2l, Wbl, tid);

    // load + split A tile [128][128] f32
#pragma unroll
    for (int i = tid; i < 4096; i += 256) {
        int r = i >> 5, c = i & 31;
        int row = m0 + r;
        float4 v = make_float4(0.f, 0.f, 0.f, 0.f);
        if (row < M) v = ((const float4*)A)[(size_t)row * 32 + c];
        __nv_bfloat16* ph = As_h + r * SA + c * 4;
        __nv_bfloat16* pl = As_l + r * SA + c * 4;
        split_store2(v.x, v.y, ph, pl);
        split_store2(v.z, v.w, ph + 2, pl + 2);
    }
    __syncthreads();

    const int lane = tid & 31, wid = tid >> 5;
    const int rowBase = (wid >> 2) * 64, colBase = (wid & 3) * 32;
    const int lrow = lane & 15, lkoff = (lane >> 4) * 8;
    const int cq = (lane & 3) * 2, rq = lane >> 2;

    float acc[4][4][4];
    gemm_pass(As_h, As_l, Wah, Wal, rowBase, colBase, lrow, lkoff, acc);

    __syncthreads();  // everyone done reading As -> reuse for h1
#pragma unroll
    for (int mi = 0; mi < 4; ++mi)
#pragma unroll
        for (int ni = 0; ni < 4; ++ni) {
            const int col = colBase + ni * 8 + cq;
            const float bb0 = b1[col], bb1 = b1[col + 1];
            const int r0 = rowBase + mi * 16 + rq, r1 = r0 + 8;
            float v00 = fmaxf(acc[mi][ni][0] + bb0, 0.f);
            float v01 = fmaxf(acc[mi][ni][1] + bb1, 0.f);
            float v10 = fmaxf(acc[mi][ni][2] + bb0, 0.f);
            float v11 = fmaxf(acc[mi][ni][3] + bb1, 0.f);
            split_store2(v00, v01, As_h + r0 * SA + col, As_l + r0 * SA + col);
            split_store2(v10, v11, As_h + r1 * SA + col, As_l + r1 * SA + col);
        }
    __syncthreads();

    gemm_pass(As_h, As_l, Wbh, Wbl, rowBase, colBase, lrow, lkoff, acc);

#pragma unroll
    for (int mi = 0; mi < 4; ++mi)
#pragma unroll
        for (int ni = 0; ni < 4; ++ni) {
            const int col = colBase + ni * 8 + cq;
            const float bb0 = b2[col], bb1 = b2[col + 1];
            const int r0 = m0 + rowBase + mi * 16 + rq, r1 = r0 + 8;
            float v00 = acc[mi][ni][0] + bb0, v01 = acc[mi][ni][1] + bb1;
            float v10 = acc[mi][ni][2] + bb0, v11 = acc[mi][ni][3] + bb1;
            if (RELU2) {
                v00 = fmaxf(v00, 0.f); v01 = fmaxf(v01, 0.f);
                v10 = fmaxf(v10, 0.f); v11 = fmaxf(v11, 0.f);
            }
            if (r0 < M) *(float2*)(C + (size_t)r0 * HD + col) = make_float2(v00, v01);
            if (r1 < M) *(float2*)(C + (size_t)r1 * HD + col) = make_float2(v10, v11);
        }
}

// ---------------- output head: C[M,64] = A[M,128] @ Wo + b -----------------
__global__ __launch_bounds__(256, 1) void gemm_out_mma(
    const float* __restrict__ A,
    const __nv_bfloat16* __restrict__ Woh, const __nv_bfloat16* __restrict__ Wol,
    const float* __restrict__ bias, float* __restrict__ C, int M) {
    extern __shared__ char smem[];
    __nv_bfloat16* As_h = (__nv_bfloat16*)smem;
    __nv_bfloat16* As_l = As_h + 128 * SA;
    __nv_bfloat16* Wh = As_l + 128 * SA;
    __nv_bfloat16* Wl = Wh + 64 * SA;

    const int tid = threadIdx.x;
    const int m0 = blockIdx.x * 128;

#pragma unroll
    for (int i = tid; i < 1024; i += 256) {  // Wo packed [64][128] bf16
        int r = i >> 4, c = i & 15;
        *(uint4*)(Wh + r * SA + c * 8) = ((const uint4*)Woh)[i];
        *(uint4*)(Wl + r * SA + c * 8) = ((const uint4*)Wol)[i];
    }
#pragma unroll
    for (int i = tid; i < 4096; i += 256) {
        int r = i >> 5, c = i & 31;
        int row = m0 + r;
        float4 v = make_float4(0.f, 0.f, 0.f, 0.f);
        if (row < M) v = ((const float4*)A)[(size_t)row * 32 + c];
        __nv_bfloat16* ph = As_h + r * SA + c * 4;
        __nv_bfloat16* pl = As_l + r * SA + c * 4;
        split_store2(v.x, v.y, ph, pl);
        split_store2(v.z, v.w, ph + 2, pl + 2);
    }
    __syncthreads();

    const int lane = tid & 31, wid = tid >> 5;
    const int rowBase = (wid >> 2) * 64, colBase = (wid & 3) * 16;
    const int lrow = lane & 15, lkoff = (lane >> 4) * 8;
    const int cq = (lane & 3) * 2, rq = lane >> 2;

    float acc[4][2][4];
#pragma unroll
    for (int mi = 0; mi < 4; ++mi)
#pragma unroll
        for (int ni = 0; ni < 2; ++ni)
#pragma unroll
            for (int q = 0; q < 4; ++q) acc[mi][ni][q] = 0.f;

#pragma unroll
    for (int ks = 0; ks < 8; ++ks) {
        const int k0 = ks * 16 + lkoff;
        uint32_t ah[4][4], al[4][4];
#pragma unroll
        for (int mi = 0; mi < 4; ++mi) {
            const int base = (rowBase + mi * 16 + lrow) * SA + k0;
            ldsm4(ah[mi], As_h + base);
            ldsm4(al[mi], As_l + base);
        }
        uint32_t bh[4], bl[4];
        {
            const int base = (colBase + lrow) * SA + k0;
            ldsm4(bh, Wh + base);
            ldsm4(bl, Wl + base);
        }
#pragma unroll
        for (int mi = 0; mi < 4; ++mi)
#pragma unroll
            for (int ni = 0; ni < 2; ++ni) {
                mma_bf16(acc[mi][ni], ah[mi], bh[ni], bh[ni + 2]);
                mma_bf16(acc[mi][ni], ah[mi], bl[ni], bl[ni + 2]);
                mma_bf16(acc[mi][ni], al[mi], bh[ni], bh[ni + 2]);
            }
    }

#pragma unroll
    for (int mi = 0; mi < 4; ++mi)
#pragma unroll
        for (int ni = 0; ni < 2; ++ni) {
            const int col = colBase + ni * 8 + cq;
            const float bb0 = bias[col], bb1 = bias[col + 1];
            const int r0 = m0 + rowBase + mi * 16 + rq, r1 = r0 + 8;
            if (r0 < M)
                *(float2*)(C + (size_t)r0 * OD + col) =
                    make_float2(acc[mi][ni][0] + bb0, acc[mi][ni][1] + bb1);
            if (r1 < M)
                *(float2*)(C + (size_t)r1 * OD + col) =
                    make_float2(acc[mi][ni][2] + bb0, acc[mi][ni][3] + bb1);
        }
}

// ---------------- weight prep kernels --------------------------------------
__global__ void fold_bn_convert_kernel(const float* __restrict__ W1,
                                       const float* __restrict__ b1,
                                       const float* __restrict__ g,
                                       const float* __restrict__ bb,
                                       const float* __restrict__ m,
                                       const float* __restrict__ v,
                                       __nv_bfloat16* __restrict__ Wh,
                                       __nv_bfloat16* __restrict__ Wl,
                                       float* __restrict__ bf) {
    int idx = blockIdx.x * 256 + threadIdx.x;  // 16384
    int k = idx >> 7, n = idx & 127;
    float s = g[n] * rsqrtf(v[n] + 1e-5f);
    float val = W1[idx] * s;
    __nv_bfloat16 h = __float2bfloat16(val);
    Wh[n * 128 + k] = h;
    Wl[n * 128 + k] = __float2bfloat16(val - __bfloat162float(h));
    if (idx < 128) bf[idx] = b1[idx] * s + bb[idx] - m[idx] * s;
}

__global__ void convert_w_kernel(const float* __restrict__ W,
                                 __nv_bfloat16* __restrict__ Wh,
                                 __nv_bfloat16* __restrict__ Wl, int N) {
    int idx = blockIdx.x * 256 + threadIdx.x;  // K*N, K=128
    int k = idx / N, n = idx - k * N;
    float val = W[idx];
    __nv_bfloat16 h = __float2bfloat16(val);
    Wh[n * 128 + k] = h;
    Wl[n * 128 + k] = __float2bfloat16(val - __bfloat162float(h));
}

// ---------------- graph kernels --------------------------------------------
__global__ void copy4_kernel(const float4* __restrict__ s,
                             float4* __restrict__ d, int n) {
    int i = blockIdx.x * 256 + threadIdx.x;
    if (i < n) d[i] = s[i];
}

__global__ void scatter_add4_kernel(const int* __restrict__ srcs,
                                    const int* __restrict__ dsts,
                                    const float* __restrict__ x,
                                    float* __restrict__ agg, int E) {
    unsigned t = blockIdx.x * 256u + threadIdx.x;
    unsigned e = t >> 5, lane = t & 31u;
    if (e >= (unsigned)E) return;
    int s = srcs[e], d = dsts[e];
    float4 v = ((const float4*)(x + (size_t)s * HD))[lane];
    float* dp = agg + (size_t)d * HD + lane * 4;
    asm volatile("red.global.add.v4.f32 [%0], {%1,%2,%3,%4};" ::"l"(dp),
                 "f"(v.x), "f"(v.y), "f"(v.z), "f"(v.w)
                 : "memory");
}

__global__ void pair_gather_kernel(const int* __restrict__ ep,
                                   const float* __restrict__ y,
                                   float* __restrict__ h, int E) {
    unsigned t = blockIdx.x * 256u + threadIdx.x;
    unsigned e = t >> 5, lane = t & 31u;
    if (e >= (unsigned)E) return;
    int i0 = ep[2 * e], i1 = ep[2 * e + 1];
    float4 a = ((const float4*)(y + (size_t)i0 * HD))[lane];
    float4 b = ((const float4*)(y + (size_t)i1 * HD))[lane];
    a.x += b.x; a.y += b.y; a.z += b.z; a.w += b.w;
    ((float4*)(h + (size_t)e * HD))[lane] = a;
}

// ---------------------------------------------------------------------------
extern "C" void kernel_launch(void* const* d_in, const int* in_sizes, int n_in,
                              void* d_out, int out_size) {
    const int*   edge_index = (const int*)d_in[0];
    const float* x_orig     = (const float*)d_in[1];
    const int*   ei_orig    = (const int*)d_in[2];
    const int*   edge_pairs = (const int*)d_in[3];
    const float* init_W1 = (const float*)d_in[4];
    const float* init_b1 = (const float*)d_in[5];
    const float* init_g  = (const float*)d_in[6];
    const float* init_bb = (const float*)d_in[7];
    const float* init_m  = (const float*)d_in[8];
    const float* init_v  = (const float*)d_in[9];
    const float* init_W2 = (const float*)d_in[10];
    const float* init_b2 = (const float*)d_in[11];
    const float* gin_W1  = (const float*)d_in[12];
    const float* gin_b1  = (const float*)d_in[13];
    const float* gin_g   = (const float*)d_in[14];
    const float* gin_bb  = (const float*)d_in[15];
    const float* gin_m   = (const float*)d_in[16];
    const float* gin_v   = (const float*)d_in[17];
    const float* gin_W2  = (const float*)d_in[18];
    const float* gin_b2  = (const float*)d_in[19];
    const float* mlp_W1  = (const float*)d_in[20];
    const float* mlp_b1  = (const float*)d_in[21];
    const float* mlp_g   = (const float*)d_in[22];
    const float* mlp_bb  = (const float*)d_in[23];
    const float* mlp_m   = (const float*)d_in[24];
    const float* mlp_v   = (const float*)d_in[25];
    const float* mlp_W2  = (const float*)d_in[26];
    const float* mlp_b2  = (const float*)d_in[27];
    const float* out_W   = (const float*)d_in[28];
    const float* out_b   = (const float*)d_in[29];
    float* out = (float*)d_out;

    float *nodeA, *nodeC, *edgeA, *edgeB, *bf;
    __nv_bfloat16 *W1h, *W1l, *W2h, *W2l, *Woh, *Wol;
    cudaGetSymbolAddress((void**)&nodeA, g_nodeA);
    cudaGetSymbolAddress((void**)&nodeC, g_nodeC);
    cudaGetSymbolAddress((void**)&edgeA, g_edgeA);
    cudaGetSymbolAddress((void**)&edgeB, g_edgeB);
    cudaGetSymbolAddress((void**)&bf, g_bf);
    cudaGetSymbolAddress((void**)&W1h, g_W1h);
    cudaGetSymbolAddress((void**)&W1l, g_W1l);
    cudaGetSymbolAddress((void**)&W2h, g_W2h);
    cudaGetSymbolAddress((void**)&W2l, g_W2l);
    cudaGetSymbolAddress((void**)&Woh, g_Woh);
    cudaGetSymbolAddress((void**)&Wol, g_Wol);

    const int SMEM_F = 6 * 128 * SA * 2;                  // 208896 B
    const int SMEM_O = (2 * 128 * SA + 2 * 64 * SA) * 2;  // 104448 B
    cudaFuncSetAttribute(fused2_mma<true>,
                         cudaFuncAttributeMaxDynamicSharedMemorySize, SMEM_F);
    cudaFuncSetAttribute(fused2_mma<false>,
                         cudaFuncAttributeMaxDynamicSharedMemorySize, SMEM_F);
    cudaFuncSetAttribute(gemm_out_mma,
                         cudaFuncAttributeMaxDynamicSharedMemorySize, SMEM_O);

    const int gridN = (NN + 127) / 128;   // 782
    const int gridE = (EO + 127) / 128;   // 4688
    const int cpN = (NN * 32 + 255) / 256;
    const int cpE = (EO * 32 + 255) / 256;
    const int scO = ((unsigned)EO * 32u + 255u) / 256u;
    const int scL = ((unsigned)EL * 32u + 255u) / 256u;

    // ---- Stage A: 2 GIN layers on original graph --------------------------
    const float* x = x_orig;
    for (int i = 0; i < 2; ++i) {
        copy4_kernel<<<cpN, 256>>>((const float4*)x, (float4*)nodeC, NN * 32);
        scatter_add4_kernel<<<scO, 256>>>(ei_orig, ei_orig + EO, x, nodeC, EO);
        fold_bn_convert_kernel<<<64, 256>>>(init_W1 + i * HD * HD, init_b1 + i * HD,
                                            init_g + i * HD, init_bb + i * HD,
                                            init_m + i * HD, init_v + i * HD,
                                            W1h, W1l, bf);
        convert_w_kernel<<<64, 256>>>(init_W2 + i * HD * HD, W2h, W2l, HD);
        fused2_mma<true><<<gridN, 256, SMEM_F>>>(nodeC, W1h, W1l, W2h, W2l,
                                                 bf, init_b2 + i * HD, nodeA, NN);
        x = nodeA;
    }

    // ---- Stage B: node MLP (once per node) ---------------------------------
    fold_bn_convert_kernel<<<64, 256>>>(mlp_W1, mlp_b1, mlp_g, mlp_bb, mlp_m,
                                        mlp_v, W1h, W1l, bf);
    convert_w_kernel<<<64, 256>>>(mlp_W2, W2h, W2l, HD);
    fused2_mma<false><<<gridN, 256, SMEM_F>>>(nodeA, W1h, W1l, W2h, W2l,
                                              bf, mlp_b2, nodeC, NN);

    // ---- Stage C: lift onto line graph -------------------------------------
    pair_gather_kernel<<<scO, 256>>>(edge_pairs, nodeC, edgeA, EO);

    // ---- Stage D: 2 GIN layers on line graph -------------------------------
    for (int i = 0; i < 2; ++i) {
        copy4_kernel<<<cpE, 256>>>((const float4*)edgeA, (float4*)edgeB, EO * 32);
        scatter_add4_kernel<<<scL, 256>>>(edge_index, edge_index + EL, edgeA, edgeB, EL);
        fold_bn_convert_kernel<<<64, 256>>>(gin_W1 + i * HD * HD, gin_b1 + i * HD,
                                            gin_g + i * HD, gin_bb + i * HD,
                                            gin_m + i * HD, gin_v + i * HD,
                                            W1h, W1l, bf);
        convert_w_kernel<<<64, 256>>>(gin_W2 + i * HD * HD, W2h, W2l, HD);
        fused2_mma<true><<<gridE, 256, SMEM_F>>>(edgeB, W1h, W1l, W2h, W2l,
                                                 bf, gin_b2 + i * HD, edgeA, EO);
    }

    // ---- Stage E: output head ----------------------------------------------
    convert_w_kernel<<<32, 256>>>(out_W, Woh, Wol, OD);
    gemm_out_mma<<<gridE, 256, SMEM_O>>>(edgeA, Woh, Wol, out_b, out, EO);
}